// round 11
// baseline (speedup 1.0000x reference)
#include <cuda_runtime.h>

// DataWindowLoss: mean(|box5(x) - box5(y)|), padding=4, x/y: [64,1,512,512] fp32.
// box(x)-box(y) = box(x-y); separable 5x5 box; |c*s| = c*|s|.
// Register-resident streaming: each thread owns 8 output columns, shfl halo,
// incremental horizontal + vertical box sums, no smem / no barriers in hot loop.

#define BATCH   64
#define H       512
#define W       512
#define OW      516
#define OH      516
#define G_ROWS  (BATCH * OH)     // 33024
#define GX      148
#define WPB     4                // warps per block
#define BLOCK   (WPB * 32)       // 128
#define NSTRIPS (GX * WPB)       // 592 row-strips (~56 rows each)
#define NBTOT   (GX * 2)         // 296 blocks = one balanced wave

__device__ double   g_acc;       // zero at load; reset by last block each call
__device__ unsigned g_count;

__global__ __launch_bounds__(BLOCK, 2)
void box_loss_kernel(const float* __restrict__ x, const float* __restrict__ y,
                     float* __restrict__ out) {
    __shared__ float wsum[WPB];

    const int tid  = threadIdx.x;
    const int warp = tid >> 5, lane = tid & 31;
    const int slab = blockIdx.y;                  // 0: cols 0..255, 1: 256..515
    const int strip = blockIdx.x * WPB + warp;
    const int base  = slab * 256 + lane * 8;      // first input col owned
    const bool is_e = (slab == 1) && (lane == 0); // needs gmem edge halo

    const int g0 = (int)((long long)strip       * G_ROWS / NSTRIPS);
    const int g1 = (int)((long long)(strip + 1) * G_ROWS / NSTRIPS);

    float  ring[5][8], v[8];      // h-history ring + running vertical sums
    float  tring[5][4], vt[4];    // tail columns 512..515 (slab1 lane31)
    float  acc = 0.f, tacc = 0.f;
    float4 bx[2][2], by[2][2], ex[2], ey[2];

    int g = g0;
    while (g < g1) {                               // per-batch segment (<=2)
        const int b  = g / OH;
        const int s0 = g - b * OH;
        int n = g1 - g; if (n > OH - s0) n = OH - s0;
        const int vrb   = s0 - 4;                  // first virtual input row
        const int steps = n + 4;
        const float* xb = x + (size_t)b * (H * W);
        const float* yb = y + (size_t)b * (H * W);

        #pragma unroll
        for (int k = 0; k < 5; ++k) {
            #pragma unroll
            for (int j = 0; j < 8; ++j) ring[k][j] = 0.f;
            #pragma unroll
            for (int j = 0; j < 4; ++j) tring[k][j] = 0.f;
        }
        #pragma unroll
        for (int j = 0; j < 8; ++j) v[j] = 0.f;
        #pragma unroll
        for (int j = 0; j < 4; ++j) vt[j] = 0.f;

        // Prime loads for steps 0,1 (steps >= 5 always).
        #pragma unroll
        for (int u = 0; u < 2; ++u) {
            const int r = vrb + u;
            if ((unsigned)r < (unsigned)H) {
                const float* rp = xb + (size_t)r * W;
                const float* rq = yb + (size_t)r * W;
                bx[u][0] = __ldcs((const float4*)(rp + base));
                bx[u][1] = __ldcs((const float4*)(rp + base + 4));
                by[u][0] = __ldcs((const float4*)(rq + base));
                by[u][1] = __ldcs((const float4*)(rq + base + 4));
                if (is_e) { ex[u] = __ldcs((const float4*)(rp + 252));
                            ey[u] = __ldcs((const float4*)(rq + 252)); }
            }
        }

        for (int t0 = 0; t0 < steps; t0 += 10) {
            #pragma unroll
            for (int u = 0; u < 10; ++u) {
                const int tt = t0 + u;
                const int p  = u & 1;              // buffer parity (static)
                const int k  = u % 5;              // ring slot (static)
                const int r  = vrb + tt;
                const bool live = (tt < steps) && ((unsigned)r < (unsigned)H);

                float h[8], th[4];
                if (live) {
                    float dd[12];                  // dd[i] = d[base-4+i]
                    dd[4]  = bx[p][0].x - by[p][0].x;
                    dd[5]  = bx[p][0].y - by[p][0].y;
                    dd[6]  = bx[p][0].z - by[p][0].z;
                    dd[7]  = bx[p][0].w - by[p][0].w;
                    dd[8]  = bx[p][1].x - by[p][1].x;
                    dd[9]  = bx[p][1].y - by[p][1].y;
                    dd[10] = bx[p][1].z - by[p][1].z;
                    dd[11] = bx[p][1].w - by[p][1].w;
                    // edge diffs (meaningful on slab1 lane0 only; read ex[p]
                    // BEFORE the prefetch below overwrites it)
                    float e0 = ex[p].x - ey[p].x, e1 = ex[p].y - ey[p].y;
                    float e2 = ex[p].z - ey[p].z, e3 = ex[p].w - ey[p].w;
                    // neighbor halo: prev lane's top 4 diffs
                    float s0f = __shfl_up_sync(0xffffffffu, dd[8], 1);
                    float s1f = __shfl_up_sync(0xffffffffu, dd[9], 1);
                    float s2f = __shfl_up_sync(0xffffffffu, dd[10], 1);
                    float s3f = __shfl_up_sync(0xffffffffu, dd[11], 1);
                    if (lane == 0) {
                        if (slab == 1) { s0f = e0; s1f = e1; s2f = e2; s3f = e3; }
                        else           { s0f = s1f = s2f = s3f = 0.f; }
                    }
                    dd[0] = s0f; dd[1] = s1f; dd[2] = s2f; dd[3] = s3f;
                    // horizontal 5-sum, incremental: h[j] = sum dd[j..j+4]
                    h[0] = ((dd[0] + dd[1]) + (dd[2] + dd[3])) + dd[4];
                    #pragma unroll
                    for (int j = 1; j < 8; ++j) h[j] = h[j-1] - dd[j-1] + dd[j+4];
                    // tail cols 512..515: suffix windows (valid on lane31/slab1)
                    th[0] = h[7] - dd[7];
                    th[1] = th[0] - dd[8];
                    th[2] = th[1] - dd[9];
                    th[3] = th[2] - dd[10];
                } else {
                    #pragma unroll
                    for (int j = 0; j < 8; ++j) h[j] = 0.f;
                    #pragma unroll
                    for (int j = 0; j < 4; ++j) th[j] = 0.f;
                }

                // Prefetch step tt+2 into the buffer just consumed.
                {
                    const int t2 = tt + 2;
                    const int r2 = vrb + t2;
                    if (t2 < steps && (unsigned)r2 < (unsigned)H) {
                        const float* rp = xb + (size_t)r2 * W;
                        const float* rq = yb + (size_t)r2 * W;
                        bx[p][0] = __ldcs((const float4*)(rp + base));
                        bx[p][1] = __ldcs((const float4*)(rp + base + 4));
                        by[p][0] = __ldcs((const float4*)(rq + base));
                        by[p][1] = __ldcs((const float4*)(rq + base + 4));
                        if (is_e) { ex[p] = __ldcs((const float4*)(rp + 252));
                                    ey[p] = __ldcs((const float4*)(rq + 252)); }
                    }
                }

                // Vertical incremental box: v += h_new - h_{t-5}
                #pragma unroll
                for (int j = 0; j < 8; ++j) { v[j] += h[j] - ring[k][j]; ring[k][j] = h[j]; }
                #pragma unroll
                for (int j = 0; j < 4; ++j) { vt[j] += th[j] - tring[k][j]; tring[k][j] = th[j]; }

                if (tt >= 4 && tt < steps) {       // output row o = s0 + tt - 4
                    float a = 0.f;
                    #pragma unroll
                    for (int j = 0; j < 8; ++j) a += fabsf(v[j]);
                    acc += a;
                    tacc += fabsf(vt[0]) + fabsf(vt[1]) + fabsf(vt[2]) + fabsf(vt[3]);
                }
            }
        }
        g += n;
    }

    // Tail columns count only from slab1 lane31.
    if (slab == 1 && lane == 31) acc += tacc;

    // Warp reduce (lanes hold disjoint columns), then block reduce + atomic.
    #pragma unroll
    for (int off = 16; off; off >>= 1)
        acc += __shfl_xor_sync(0xffffffffu, acc, off);
    if (lane == 0) wsum[warp] = acc;
    __syncthreads();
    if (tid == 0) {
        float t = wsum[0] + wsum[1] + wsum[2] + wsum[3];
        atomicAdd(&g_acc, (double)t);
        __threadfence();
        const unsigned ticket = atomicAdd(&g_count, 1u);
        if (ticket == NBTOT - 1) {                 // last block finalizes + resets
            const double total = atomicAdd(&g_acc, 0.0);
            out[0] = (float)(total / 25.0 / ((double)BATCH * OH * OW));
            g_acc = 0.0;
            __threadfence();
            g_count = 0u;
        }
    }
}

extern "C" void kernel_launch(void* const* d_in, const int* in_sizes, int n_in,
                              void* d_out, int out_size) {
    (void)in_sizes; (void)n_in; (void)out_size;
    const float* x = (const float*)d_in[0];
    const float* y = (const float*)d_in[1];
    float* out = (float*)d_out;
    dim3 grid(GX, 2);
    box_loss_kernel<<<grid, BLOCK>>>(x, y, out);
}

// round 13
// speedup vs baseline: 1.5606x; 1.5606x over previous
#include <cuda_runtime.h>

// DataWindowLoss: mean(|box5(x) - box5(y)|), padding=4, x/y: [64,1,512,512] fp32.
// box(x)-box(y) = box(x-y); separable 5x5 box; |c*s| = c*|s|.
// Smem-pipelined streaming: 640-thread blocks, 5-row chunks (static ring slots),
// 129 owner threads consume 4 output columns each via 2x LDS.128 + incremental
// horizontal/vertical box sums. One balanced wave of 296 blocks, fused finalize.

#define BATCH   64
#define H       512
#define W       512
#define OW      516
#define OH      516
#define G_ROWS  (BATCH * OH)        // 33024 global output rows
#define NB      296                 // 2 blocks/SM * 148 SMs: one balanced wave
#define BLOCK   640                 // 20 warps; 5 rows * 128 float4-loaders
#define NWARPS  (BLOCK / 32)
#define CR      5                   // rows per chunk -> ring slot == rr (static)
#define ROWLEN  520                 // 4 zero-pad + 512 + 4 zero-pad
#define NOWN    129                 // owner threads, 4 output cols each (516)

__device__ double   g_acc;          // zero at module load; reset by last block
__device__ unsigned g_count;

__global__ __launch_bounds__(BLOCK, 2)
void box_loss_kernel(const float* __restrict__ x, const float* __restrict__ y,
                     float* __restrict__ out) {
    __shared__ float sbuf[2][CR][ROWLEN];   // 20.8 KB double-buffered diff rows
    __shared__ float wsum[NWARPS];

    const int tid = threadIdx.x;
    const int row = tid >> 7;               // 0..4 : chunk row this thread loads
    const int col = (tid & 127) << 2;       // 0..508 : float4 column

    // Zero the pads once: sd[r][0..3] and sd[r][516..519], both buffers.
    if (tid < 2 * CR * 8) {                 // 80 threads, 8 pad floats each
        const int buf = tid / (CR * 8);
        const int rr  = (tid / 8) % CR;
        const int k   = tid & 7;            // 0..7 -> pad index
        sbuf[buf][rr][k < 4 ? k : 512 + k] = 0.f;
    }

    float acc = 0.f;

    // Balanced contiguous slice of the global (batch-major) output-row space.
    const int g0 = (int)((long long)blockIdx.x       * G_ROWS / NB);
    const int g1 = (int)((long long)(blockIdx.x + 1) * G_ROWS / NB);

    int g = g0;
    while (g < g1) {                         // per-batch segment (<=2 per block)
        const int b  = g / OH;
        const int s0 = g - b * OH;
        int n = g1 - g;
        if (n > OH - s0) n = OH - s0;
        const int steps  = n + 4;            // virtual input rows (top halo)
        const int nchunk = (steps + CR - 1) / CR;
        const int vrb    = s0 - 4;
        const float* xb = x + (size_t)b * (H * W);
        const float* yb = y + (size_t)b * (H * W);

        __syncthreads();                     // smem reuse fence (segment start)

        // Preload chunk 0 into registers.
        float4 rx = make_float4(0.f, 0.f, 0.f, 0.f), ry = rx;
        {
            const int gr = vrb + row;
            if (row < steps && (unsigned)gr < (unsigned)H) {
                rx = __ldcs((const float4*)(xb + (size_t)gr * W + col));
                ry = __ldcs((const float4*)(yb + (size_t)gr * W + col));
            }
        }

        float ring[CR][4];                   // h history: slot rr is static
        float v0 = 0.f, v1 = 0.f, v2 = 0.f, v3 = 0.f;
        #pragma unroll
        for (int k = 0; k < CR; ++k)
            ring[k][0] = ring[k][1] = ring[k][2] = ring[k][3] = 0.f;

        #pragma unroll 1
        for (int c = 0; c < nchunk; ++c) {
            const int p = c & 1;

            // Commit staged diff to smem buffer p.
            {
                float4 d;
                d.x = rx.x - ry.x;  d.y = rx.y - ry.y;
                d.z = rx.z - ry.z;  d.w = rx.w - ry.w;
                *(float4*)&sbuf[p][row][4 + col] = d;
            }

            // Prefetch chunk c+1 (hidden under this chunk's compute).
            rx = make_float4(0.f, 0.f, 0.f, 0.f); ry = rx;
            if (c + 1 < nchunk) {
                const int st = (c + 1) * CR + row;
                const int gr = vrb + st;
                if (st < steps && (unsigned)gr < (unsigned)H) {
                    rx = __ldcs((const float4*)(xb + (size_t)gr * W + col));
                    ry = __ldcs((const float4*)(yb + (size_t)gr * W + col));
                }
            }

            __syncthreads();                 // one barrier per chunk

            // Owners consume CR rows: 4 output cols each.
            if (tid < NOWN) {
                const float* qb = &sbuf[p][0][tid << 2];
                const int base = c * CR;
                #pragma unroll
                for (int rr = 0; rr < CR; ++rr) {
                    const float* q = qb + rr * ROWLEN;
                    const float4 a  = *(const float4*)q;        // sd[4t..4t+3]
                    const float4 bq = *(const float4*)(q + 4);  // sd[4t+4..4t+7]
                    // horizontal 5-sums, incremental
                    const float h0 = ((a.x + a.y) + (a.z + a.w)) + bq.x;
                    const float h1 = h0 - a.x + bq.y;
                    const float h2 = h1 - a.y + bq.z;
                    const float h3 = h2 - a.z + bq.w;
                    // vertical incremental: v += h_new - h_{t-5}
                    v0 += h0 - ring[rr][0];  ring[rr][0] = h0;
                    v1 += h1 - ring[rr][1];  ring[rr][1] = h1;
                    v2 += h2 - ring[rr][2];  ring[rr][2] = h2;
                    v3 += h3 - ring[rr][3];  ring[rr][3] = h3;
                    const int step = base + rr;
                    if (step >= 4 && step < steps)
                        acc += fabsf(v0) + fabsf(v1) + fabsf(v2) + fabsf(v3);
                }
            }
            // Double buffering: next STS targets the other buffer; reuse of
            // this one is fenced by the next chunk's barrier.
        }
        g += n;
    }

    // Block reduction -> one double atomic per block.
    #pragma unroll
    for (int off = 16; off; off >>= 1)
        acc += __shfl_xor_sync(0xffffffffu, acc, off);
    if ((tid & 31) == 0) wsum[tid >> 5] = acc;
    __syncthreads();
    if (tid == 0) {
        float t = 0.f;
        #pragma unroll
        for (int w = 0; w < NWARPS; ++w) t += wsum[w];
        atomicAdd(&g_acc, (double)t);
        __threadfence();
        const unsigned ticket = atomicAdd(&g_count, 1u);
        if (ticket == NB - 1) {              // last block finalizes + resets
            const double total = atomicAdd(&g_acc, 0.0);
            out[0] = (float)(total / 25.0 / ((double)BATCH * OH * OW));
            g_acc = 0.0;
            __threadfence();
            g_count = 0u;
        }
    }
}

extern "C" void kernel_launch(void* const* d_in, const int* in_sizes, int n_in,
                              void* d_out, int out_size) {
    (void)in_sizes; (void)n_in; (void)out_size;
    const float* x = (const float*)d_in[0];
    const float* y = (const float*)d_in[1];
    float* out = (float*)d_out;
    box_loss_kernel<<<NB, BLOCK>>>(x, y, out);
}

// round 14
// speedup vs baseline: 1.7796x; 1.1404x over previous
#include <cuda_runtime.h>

// DataWindowLoss: mean(|box5(x) - box5(y)|), padding=4, x/y: [64,1,512,512] fp32.
// box(x)-box(y) = box(x-y); separable 5x5 box; |c*s| = c*|s|.
// 2-chunk-deep register prefetch (covers DRAM latency), 4-row chunks, double-
// buffered diff smem, 258 owner threads x 2 cols, P-carry vertical box.

#define BATCH   64
#define H       512
#define W       512
#define OW      516
#define OH      516
#define G_ROWS  (BATCH * OH)        // 33024
#define NB      296                 // 2 blocks/SM * 148 SMs: one balanced wave
#define BLOCK   512                 // 16 warps
#define NWARPS  (BLOCK / 32)
#define CR      4                   // rows/chunk: 4*128 float4 == 512 threads
#define ROWLEN  520                 // 4 zero-pad + 512 + 4 zero-pad
#define NOWN    258                 // owners, 2 output cols each (516)

__device__ double   g_acc;
__device__ unsigned g_count;

// Stage one chunk-row of x,y into (RX,RY); zeros outside the image.
#define LOADC(ST, RX, RY) do {                                                \
    RX = make_float4(0.f, 0.f, 0.f, 0.f); RY = RX;                            \
    const int _gr = vrb + (ST);                                               \
    if ((unsigned)_gr < (unsigned)H) {                                        \
        RX = __ldcs((const float4*)(xr + (size_t)_gr * W));                   \
        RY = __ldcs((const float4*)(yr + (size_t)_gr * W));                   \
    }                                                                         \
} while (0)

// One pipeline sub-body: commit staged chunk CC to buffer BUF, prefetch CC+2
// into the same registers, barrier, consume buffer BUF.
#define SUBBODY(CC, BUF, RX, RY) do {                                         \
    {   float4 _d;                                                            \
        _d.x = RX.x - RY.x; _d.y = RX.y - RY.y;                               \
        _d.z = RX.z - RY.z; _d.w = RX.w - RY.w;                               \
        *(float4*)&sbuf[BUF][lrow][4 + lcol] = _d;                            \
    }                                                                         \
    LOADC(((CC) + 2) * CR + lrow, RX, RY);                                    \
    __syncthreads();                                                          \
    if (tid < NOWN) {                                                         \
        const float* _q = &sbuf[BUF][0][tid << 1];                            \
        const int _base = (CC) * CR;                                          \
        float gA[CR], gB[CR];                                                 \
        _Pragma("unroll")                                                     \
        for (int _rr = 0; _rr < CR; ++_rr) {                                  \
            const float* _r = _q + _rr * ROWLEN;                              \
            const float2 _d0 = *(const float2*)(_r);                          \
            const float2 _d1 = *(const float2*)(_r + 2);                      \
            const float2 _d2 = *(const float2*)(_r + 4);                      \
            const float _hA = ((_d0.x + _d0.y) + (_d1.x + _d1.y)) + _d2.x;    \
            gA[_rr] = _hA;                                                    \
            gB[_rr] = _hA - _d0.x + _d2.y;                                    \
        }                                                                     \
        v0 += gA[0] - P5a;  v1 += gB[0] - P5b;                                \
        if (_base + 0 >= 4 && _base + 0 < steps) acc += fabsf(v0) + fabsf(v1);\
        v0 += gA[1] - P4a;  v1 += gB[1] - P4b;                                \
        if (_base + 1 >= 4 && _base + 1 < steps) acc += fabsf(v0) + fabsf(v1);\
        v0 += gA[2] - P3a;  v1 += gB[2] - P3b;                                \
        if (_base + 2 >= 4 && _base + 2 < steps) acc += fabsf(v0) + fabsf(v1);\
        v0 += gA[3] - P2a;  v1 += gB[3] - P2b;                                \
        if (_base + 3 >= 4 && _base + 3 < steps) acc += fabsf(v0) + fabsf(v1);\
        P5a = P1a; P4a = gA[0]; P3a = gA[1]; P2a = gA[2]; P1a = gA[3];        \
        P5b = P1b; P4b = gB[0]; P3b = gB[1]; P2b = gB[2]; P1b = gB[3];        \
    }                                                                         \
} while (0)

__global__ __launch_bounds__(BLOCK, 2)
void box_loss_kernel(const float* __restrict__ x, const float* __restrict__ y,
                     float* __restrict__ out) {
    __shared__ float sbuf[2][CR][ROWLEN];   // 16.6 KB double-buffered diff rows
    __shared__ float wsum[NWARPS];

    const int tid  = threadIdx.x;
    const int lrow = tid >> 7;              // 0..3 : chunk row this thread loads
    const int lcol = (tid & 127) << 2;      // 0..508 : float4 column

    // Zero the pads once: [0..3] and [516..519] per row, both buffers (64 thr).
    if (tid < 64) {
        const int buf = tid >> 5, rr = (tid >> 3) & 3, k = tid & 7;
        sbuf[buf][rr][k < 4 ? k : 512 + k] = 0.f;
    }

    float acc = 0.f;

    const int g0 = (int)((long long)blockIdx.x       * G_ROWS / NB);
    const int g1 = (int)((long long)(blockIdx.x + 1) * G_ROWS / NB);

    int g = g0;
    while (g < g1) {                         // per-batch segment (<=2 per block)
        const int b  = g / OH;
        const int s0 = g - b * OH;
        int n = g1 - g;
        if (n > OH - s0) n = OH - s0;
        const int steps  = n + 4;
        const int nchunk = (steps + CR - 1) / CR;
        const int vrb    = s0 - 4;
        const float* xr = x + (size_t)b * (H * W) + lcol;
        const float* yr = y + (size_t)b * (H * W) + lcol;

        __syncthreads();                     // smem reuse fence (segment start)

        float4 ax, ay, bx4, by4;
        LOADC(lrow,      ax,  ay);           // stage chunk 0
        LOADC(CR + lrow, bx4, by4);          // stage chunk 1

        float P1a=0.f,P2a=0.f,P3a=0.f,P4a=0.f,P5a=0.f;
        float P1b=0.f,P2b=0.f,P3b=0.f,P4b=0.f,P5b=0.f;
        float v0=0.f, v1=0.f;

        #pragma unroll 1
        for (int c = 0; c < nchunk; c += 2) {
            SUBBODY(c, 0, ax, ay);
            if (c + 1 < nchunk)
                SUBBODY(c + 1, 1, bx4, by4);
        }
        g += n;
    }

    // Block reduction -> one double atomic per block.
    #pragma unroll
    for (int off = 16; off; off >>= 1)
        acc += __shfl_xor_sync(0xffffffffu, acc, off);
    if ((tid & 31) == 0) wsum[tid >> 5] = acc;
    __syncthreads();
    if (tid == 0) {
        float t = 0.f;
        #pragma unroll
        for (int w = 0; w < NWARPS; ++w) t += wsum[w];
        atomicAdd(&g_acc, (double)t);
        __threadfence();
        const unsigned ticket = atomicAdd(&g_count, 1u);
        if (ticket == NB - 1) {              // last block finalizes + resets
            const double total = atomicAdd(&g_acc, 0.0);
            out[0] = (float)(total / 25.0 / ((double)BATCH * OH * OW));
            g_acc = 0.0;
            __threadfence();
            g_count = 0u;
        }
    }
}

extern "C" void kernel_launch(void* const* d_in, const int* in_sizes, int n_in,
                              void* d_out, int out_size) {
    (void)in_sizes; (void)n_in; (void)out_size;
    const float* x = (const float*)d_in[0];
    const float* y = (const float*)d_in[1];
    float* out = (float*)d_out;
    box_loss_kernel<<<NB, BLOCK>>>(x, y, out);
}